// round 1
// baseline (speedup 1.0000x reference)
#include <cuda_runtime.h>
#include <math.h>
#include <stdint.h>
#include <stddef.h>

#define BB 256
#define TT 512
#define IN0 64
#define HH 128
#define GG 384   /* 3*H */

// ---------------- scratch (device globals; no allocation allowed) ----------
__device__ float g_xw0f[(size_t)BB * TT * GG];
__device__ float g_xw0b[(size_t)BB * TT * GG];
__device__ float g_h0  [(size_t)BB * TT * 2 * HH];
__device__ float g_xw1f[(size_t)BB * TT * GG];
__device__ float g_h1f [BB * HH];
__device__ float g_WT1b[2 * HH * GG];   // Wih1b transposed: [256][384]

__device__ __forceinline__ float sigf(float x) { return 1.f / (1.f + __expf(-x)); }
__device__ __forceinline__ float tanhfast(float x) { return 2.f / (1.f + __expf(-2.f * x)) - 1.f; }

// ---------------- GEMM: C[M,384] = A[M,K] @ W[384,K]^T + bias --------------
// BM=BN=64, full-K panels in smem, 256 threads, 4x4 micro-tile (stride-16 cols/rows)
template <int K>
__global__ void __launch_bounds__(256) gemm_xw(const float* __restrict__ A,
                                               const float* __restrict__ W,
                                               const float* __restrict__ bias,
                                               float* __restrict__ C) {
    constexpr int KC = K / 4;
    extern __shared__ char smem_raw[];
    float4* As = reinterpret_cast<float4*>(smem_raw);         // [KC][64]
    float4* Ws = As + KC * 64;                                // [KC][64]
    const int tid = threadIdx.x;
    const int n0 = blockIdx.x * 64;   // 6 n-tiles
    const int m0 = blockIdx.y * 64;   // 2048 m-tiles

    #pragma unroll
    for (int i = tid; i < 64 * KC; i += 256) {
        int m = i & 63, kc = i >> 6;
        As[kc * 64 + m] = *reinterpret_cast<const float4*>(&A[(size_t)(m0 + m) * K + kc * 4]);
    }
    #pragma unroll
    for (int i = tid; i < 64 * KC; i += 256) {
        int n = i & 63, kc = i >> 6;
        Ws[kc * 64 + n] = *reinterpret_cast<const float4*>(&W[(size_t)(n0 + n) * K + kc * 4]);
    }
    __syncthreads();

    const int tx = tid & 15, ty = tid >> 4;
    float acc[4][4];
    #pragma unroll
    for (int i = 0; i < 4; i++)
        #pragma unroll
        for (int j = 0; j < 4; j++) acc[i][j] = 0.f;

    #pragma unroll 4
    for (int kc = 0; kc < KC; ++kc) {
        float4 a[4], w[4];
        #pragma unroll
        for (int i = 0; i < 4; i++) a[i] = As[kc * 64 + ty + 16 * i];
        #pragma unroll
        for (int j = 0; j < 4; j++) w[j] = Ws[kc * 64 + tx + 16 * j];
        #pragma unroll
        for (int i = 0; i < 4; i++)
            #pragma unroll
            for (int j = 0; j < 4; j++)
                acc[i][j] += a[i].x * w[j].x + a[i].y * w[j].y + a[i].z * w[j].z + a[i].w * w[j].w;
    }

    #pragma unroll
    for (int i = 0; i < 4; i++) {
        int m = m0 + ty + 16 * i;
        #pragma unroll
        for (int j = 0; j < 4; j++) {
            int n = n0 + tx + 16 * j;
            C[(size_t)m * GG + n] = acc[i][j] + bias[n];
        }
    }
}

// ---------------- GRU scan -------------------------------------------------
// One block = R batch rows of one direction. 128 threads; thread j owns hidden
// unit j (gate rows j, j+128, j+256). Whh^T resident in smem [128][385].
// blockIdx.y == 1 -> backward (reverse time) using the *_b parameter set.
template <int R, bool STORE_SEQ>
__global__ void __launch_bounds__(128) gru_scan(
    const float* __restrict__ xw_f, const float* __restrict__ xw_b,
    const float* __restrict__ Whh_f, const float* __restrict__ Whh_b,
    const float* __restrict__ bhh_f, const float* __restrict__ bhh_b,
    float* __restrict__ out_seq,     // [B,T,2H], column offset dir*H  (STORE_SEQ)
    float* __restrict__ out_final)   // [B,H]                          (!STORE_SEQ)
{
    extern __shared__ char smem_raw[];
    float* wT = reinterpret_cast<float*>(smem_raw);   // [128][385]
    float* hb = wT + 128 * 385;                       // [2][R][128] ping-pong

    const int j   = threadIdx.x;
    const int dir = blockIdx.y;
    const bool rev = (dir == 1);
    const int b0  = blockIdx.x * R;

    const float* xw  = dir ? xw_b  : xw_f;
    const float* Whh = dir ? Whh_b : Whh_f;
    const float* bhh = dir ? bhh_b : bhh_f;

    // load Whh^T (coalesced global read; pad-385 smem -> conflict-free stores)
    for (int idx = j; idx < GG * HH; idx += 128) {
        int g = idx >> 7, k = idx & 127;
        wT[k * 385 + g] = Whh[idx];
    }
    #pragma unroll
    for (int m = 0; m < R; ++m) hb[m * 128 + j] = 0.f;
    __syncthreads();

    const float bR = bhh[j], bZ = bhh[j + 128], bN = bhh[j + 256];

    // prefetch xw for the first timestep
    float pR[R], pZ[R], pN[R];
    {
        const int t0 = rev ? TT - 1 : 0;
        #pragma unroll
        for (int m = 0; m < R; ++m) {
            const float* p = xw + ((size_t)(b0 + m) * TT + t0) * GG;
            pR[m] = p[j]; pZ[m] = p[j + 128]; pN[m] = p[j + 256];
        }
    }

    int pb = 0;
    for (int it = 0; it < TT; ++it) {
        const int t = rev ? (TT - 1 - it) : it;
        float xR[R], xZ[R], xN[R];
        #pragma unroll
        for (int m = 0; m < R; ++m) { xR[m] = pR[m]; xZ[m] = pZ[m]; xN[m] = pN[m]; }
        if (it + 1 < TT) {
            const int tn = rev ? (TT - 2 - it) : (it + 1);
            #pragma unroll
            for (int m = 0; m < R; ++m) {
                const float* p = xw + ((size_t)(b0 + m) * TT + tn) * GG;
                pR[m] = p[j]; pZ[m] = p[j + 128]; pN[m] = p[j + 256];
            }
        }

        float aR[R], aZ[R], aN[R];
        #pragma unroll
        for (int m = 0; m < R; ++m) { aR[m] = 0.f; aZ[m] = 0.f; aN[m] = 0.f; }

        const float* hcur = hb + pb * (R * 128);
        #pragma unroll 4
        for (int k = 0; k < 128; k += 4) {
            float w0[4], w1[4], w2[4];
            #pragma unroll
            for (int c = 0; c < 4; ++c) {
                const float* wp = wT + (k + c) * 385;
                w0[c] = wp[j]; w1[c] = wp[j + 128]; w2[c] = wp[j + 256];
            }
            #pragma unroll
            for (int m = 0; m < R; ++m) {
                float4 hv = *reinterpret_cast<const float4*>(&hcur[m * 128 + k]);
                aR[m] += w0[0] * hv.x + w0[1] * hv.y + w0[2] * hv.z + w0[3] * hv.w;
                aZ[m] += w1[0] * hv.x + w1[1] * hv.y + w1[2] * hv.z + w1[3] * hv.w;
                aN[m] += w2[0] * hv.x + w2[1] * hv.y + w2[2] * hv.z + w2[3] * hv.w;
            }
        }

        float* hnx = hb + (pb ^ 1) * (R * 128);
        #pragma unroll
        for (int m = 0; m < R; ++m) {
            float r = sigf(xR[m] + bR + aR[m]);
            float z = sigf(xZ[m] + bZ + aZ[m]);
            float n = tanhfast(xN[m] + r * (bN + aN[m]));
            float hold = hcur[m * 128 + j];
            float hnew = n + z * (hold - n);
            hnx[m * 128 + j] = hnew;
            if (STORE_SEQ)
                out_seq[((size_t)(b0 + m) * TT + t) * (2 * HH) + dir * HH + j] = hnew;
        }
        __syncthreads();
        pb ^= 1;
    }

    if (!STORE_SEQ) {
        #pragma unroll
        for (int m = 0; m < R; ++m)
            out_final[(b0 + m) * HH + j] = hb[pb * (R * 128) + m * 128 + j];
    }
}

// ---------------- transpose Wih1b [384,256] -> [256,384] --------------------
__global__ void transpose_w(const float* __restrict__ W, float* __restrict__ WT) {
    __shared__ float tile[32][33];
    int x = blockIdx.x * 32 + threadIdx.x;  // k (0..255)
    int y = blockIdx.y * 32 + threadIdx.y;  // g (0..383)
    tile[threadIdx.y][threadIdx.x] = W[y * 256 + x];
    __syncthreads();
    int xo = blockIdx.y * 32 + threadIdx.x; // g
    int yo = blockIdx.x * 32 + threadIdx.y; // k
    WT[yo * 384 + xo] = tile[threadIdx.x][threadIdx.y];
}

// ---------------- epilogue: layer-1 backward first step + ReLU + FC --------
__global__ void __launch_bounds__(128) final_kernel(
    const float* __restrict__ h0,     // [B,T,256] layer-0 concat
    const float* __restrict__ h1f,    // [B,128]   layer-1 fwd final state
    const float* __restrict__ WT,     // [256][384] = Wih1b^T
    const float* __restrict__ bih, const float* __restrict__ bhh,
    const float* __restrict__ fc_w, const float* __restrict__ fc_b,
    float* __restrict__ out)          // [B,2]
{
    const int b = blockIdx.x, j = threadIdx.x;
    __shared__ float x1[256];
    __shared__ float red[2][128];

    const float* src = h0 + ((size_t)b * TT + (TT - 1)) * 256;
    x1[j] = src[j];
    x1[j + 128] = src[j + 128];
    __syncthreads();

    float a0 = bih[j], a1 = bih[j + 128], a2 = bih[j + 256];
    #pragma unroll 4
    for (int k = 0; k < 256; ++k) {
        float xv = x1[k];
        const float* w = WT + k * 384;
        a0 += w[j] * xv; a1 += w[j + 128] * xv; a2 += w[j + 256] * xv;
    }
    // reverse-scan first step at t=T-1 with h_prev = 0
    float r = sigf(a0 + bhh[j]);
    float z = sigf(a1 + bhh[j + 128]);
    float n = tanhfast(a2 + r * bhh[j + 256]);
    float hbv = (1.f - z) * n;

    float af = fmaxf(h1f[b * HH + j], 0.f);
    float ab = fmaxf(hbv, 0.f);
    #pragma unroll
    for (int o = 0; o < 2; ++o)
        red[o][j] = af * fc_w[o * 256 + j] + ab * fc_w[o * 256 + 128 + j];
    __syncthreads();
    for (int s = 64; s > 0; s >>= 1) {
        if (j < s) { red[0][j] += red[0][j + s]; red[1][j] += red[1][j + s]; }
        __syncthreads();
    }
    if (j < 2) out[b * 2 + j] = red[j][0] + fc_b[j];
}

// ---------------- launch ----------------------------------------------------
extern "C" void kernel_launch(void* const* d_in, const int* in_sizes, int n_in,
                              void* d_out, int out_size) {
    const float* x     = (const float*)d_in[0];
    const float* Wih0f = (const float*)d_in[1];
    const float* Whh0f = (const float*)d_in[2];
    const float* bih0f = (const float*)d_in[3];
    const float* bhh0f = (const float*)d_in[4];
    const float* Wih0b = (const float*)d_in[5];
    const float* Whh0b = (const float*)d_in[6];
    const float* bih0b = (const float*)d_in[7];
    const float* bhh0b = (const float*)d_in[8];
    const float* Wih1f = (const float*)d_in[9];
    const float* Whh1f = (const float*)d_in[10];
    const float* bih1f = (const float*)d_in[11];
    const float* bhh1f = (const float*)d_in[12];
    const float* Wih1b = (const float*)d_in[13];
    const float* Whh1b = (const float*)d_in[14];
    const float* bih1b = (const float*)d_in[15];
    const float* bhh1b = (const float*)d_in[16];
    const float* fc_w  = (const float*)d_in[17];
    const float* fc_b  = (const float*)d_in[18];
    float* out = (float*)d_out;

    float *xw0f, *xw0b, *h0, *xw1f, *h1f, *WT;
    cudaGetSymbolAddress((void**)&xw0f, g_xw0f);
    cudaGetSymbolAddress((void**)&xw0b, g_xw0b);
    cudaGetSymbolAddress((void**)&h0,   g_h0);
    cudaGetSymbolAddress((void**)&xw1f, g_xw1f);
    cudaGetSymbolAddress((void**)&h1f,  g_h1f);
    cudaGetSymbolAddress((void**)&WT,   g_WT1b);

    const int SCAN_SMEM4 = (128 * 385 + 2 * 4 * 128) * 4;
    const int SCAN_SMEM2 = (128 * 385 + 2 * 2 * 128) * 4;
    cudaFuncSetAttribute(gemm_xw<64>,       cudaFuncAttributeMaxDynamicSharedMemorySize, 32768);
    cudaFuncSetAttribute(gemm_xw<256>,      cudaFuncAttributeMaxDynamicSharedMemorySize, 131072);
    cudaFuncSetAttribute(gru_scan<4,true>,  cudaFuncAttributeMaxDynamicSharedMemorySize, SCAN_SMEM4);
    cudaFuncSetAttribute(gru_scan<2,false>, cudaFuncAttributeMaxDynamicSharedMemorySize, SCAN_SMEM2);

    dim3 ggrid(6, (BB * TT) / 64);

    // layer 0 input projections (f, b)
    gemm_xw<64><<<ggrid, 256, 32768>>>(x, Wih0f, bih0f, xw0f);
    gemm_xw<64><<<ggrid, 256, 32768>>>(x, Wih0b, bih0b, xw0b);
    // transpose Wih1b for the epilogue (independent; cheap)
    transpose_w<<<dim3(8, 12), dim3(32, 32)>>>(Wih1b, WT);

    // layer 0 scans, both directions in one launch
    gru_scan<4, true><<<dim3(BB / 4, 2), 128, SCAN_SMEM4>>>(
        xw0f, xw0b, Whh0f, Whh0b, bhh0f, bhh0b, h0, nullptr);

    // layer 1 forward input projection + scan (final state only)
    gemm_xw<256><<<ggrid, 256, 131072>>>(h0, Wih1f, bih1f, xw1f);
    gru_scan<2, false><<<dim3(BB / 2, 1), 128, SCAN_SMEM2>>>(
        xw1f, nullptr, Whh1f, nullptr, bhh1f, nullptr, nullptr, h1f);

    // layer-1 backward one-step + ReLU + FC head
    final_kernel<<<BB, 128>>>(h0, h1f, WT, bih1b, bhh1b, fc_w, fc_b, out);
}